// round 14
// baseline (speedup 1.0000x reference)
#include <cuda_runtime.h>
#include <cuda_bf16.h>
#include <cstdint>
#include <cstddef>

#define B_ 16384
#define D_ 256
#define H_ 1024

// ---------------- scratch (device globals: no allocation allowed) ----------------
__device__ float g_noise[B_ * D_];
__device__ __nv_bfloat16 g_z1tb[B_ * H_];
__device__ __nv_bfloat16 g_qb[B_ * H_];
__device__ __nv_bfloat16 g_h1b[B_ * H_];
__device__ __nv_bfloat16 g_dh1b[4][B_ * H_];
__device__ __nv_bfloat16 g_h2b[4][B_ * H_];
__device__ __nv_bfloat16 g_W1b[(D_ + 1) * H_];
__device__ __nv_bfloat16 g_W2b[H_ * H_];
__device__ __nv_bfloat16 g_W3b[H_ * D_];
__device__ __nv_bfloat16 g_W3Tb[D_ * H_];
__device__ float g_trp[40][16][B_];
__device__ float g_xt[B_ * D_];
__device__ __nv_bfloat16 g_xtb[B_ * D_];
__device__ __nv_bfloat16 g_xeb[B_ * D_];
__device__ float g_xacc[B_ * D_];

// ---------------- PTX helpers ----------------
__device__ __forceinline__ uint32_t smem_u32(const void* p) {
    uint32_t a;
    asm("{ .reg .u64 t; cvta.to.shared.u64 t, %1; cvt.u32.u64 %0, t; }" : "=r"(a) : "l"(p));
    return a;
}

__device__ __forceinline__ float tanh_fast(float x) {
    float y;
    asm("tanh.approx.f32 %0, %1;" : "=f"(y) : "f"(x));
    return y;
}

#define CP_ASYNC16(dst, src) \
    asm volatile("cp.async.cg.shared.global [%0], [%1], 16;" :: "r"(dst), "l"(src) : "memory")
#define CP_COMMIT() asm volatile("cp.async.commit_group;" ::: "memory")
#define CP_WAIT(n)  asm volatile("cp.async.wait_group %0;" :: "n"(n) : "memory")

#define LDSM4(r0, r1, r2, r3, a) \
    asm volatile("ldmatrix.sync.aligned.m8n8.x4.shared.b16 {%0,%1,%2,%3}, [%4];" \
        : "=r"(r0), "=r"(r1), "=r"(r2), "=r"(r3) : "r"(a))
#define LDSM4T(r0, r1, r2, r3, a) \
    asm volatile("ldmatrix.sync.aligned.m8n8.x4.trans.shared.b16 {%0,%1,%2,%3}, [%4];" \
        : "=r"(r0), "=r"(r1), "=r"(r2), "=r"(r3) : "r"(a))

#define MMA16816(d, a, b) \
    asm volatile("mma.sync.aligned.m16n8k16.row.col.f32.bf16.bf16.f32 " \
        "{%0,%1,%2,%3}, {%4,%5,%6,%7}, {%8,%9}, {%0,%1,%2,%3};" \
        : "+f"((d)[0]), "+f"((d)[1]), "+f"((d)[2]), "+f"((d)[3]) \
        : "r"((a)[0]), "r"((a)[1]), "r"((a)[2]), "r"((a)[3]), "r"((b)[0]), "r"((b)[1]))

// ---------------- tiling ----------------
// CTA: 128 threads (4 warps, 2(M) x 2(N)); CTA tile M=128, N=NTILE (128 or 64).
// Warp tile 64 x NTILE/2. K-chunk 64, 2-stage pipeline.
// A rows: 64 bf16 = 128B pad to 144B; B rows: NTILE bf16, pad +16B (conflict-free).
#define A_BYTES 18432            // 128 rows x 144

template <bool AFP32>
__device__ __forceinline__ void stage_A(uint32_t sb, int off, const void* Ap,
                                        int K, int m0, int kc, int tid)
{
    if (AFP32) {
        const float* A = (const float*)Ap;
#pragma unroll
        for (int i = 0; i < 8; i++) {
            int id = tid + i * 128;
            int r = id >> 3, q = id & 7;
            const float* s = A + (size_t)(m0 + r) * K + kc + q * 8;
            float4 u = *(const float4*)s;
            float4 v = *(const float4*)(s + 4);
            __nv_bfloat162 p0 = __floats2bfloat162_rn(u.x, u.y);
            __nv_bfloat162 p1 = __floats2bfloat162_rn(u.z, u.w);
            __nv_bfloat162 p2 = __floats2bfloat162_rn(v.x, v.y);
            __nv_bfloat162 p3 = __floats2bfloat162_rn(v.z, v.w);
            uint32_t d = sb + off + r * 144 + q * 16;
            asm volatile("st.shared.v4.b32 [%0], {%1,%2,%3,%4};" :: "r"(d),
                "r"(*(uint32_t*)&p0), "r"(*(uint32_t*)&p1),
                "r"(*(uint32_t*)&p2), "r"(*(uint32_t*)&p3) : "memory");
        }
    } else {
        const __nv_bfloat16* A = (const __nv_bfloat16*)Ap;
#pragma unroll
        for (int i = 0; i < 8; i++) {
            int id = tid + i * 128;
            int r = id >> 3, q = id & 7;
            CP_ASYNC16(sb + off + r * 144 + q * 16,
                       A + (size_t)(m0 + r) * K + kc + q * 8);
        }
    }
}

template <int NTILE>
__device__ __forceinline__ void stage_B(uint32_t sb, int off, const __nv_bfloat16* W,
                                        int Ntot, int n0, int kc, int tid)
{
    constexpr int BROW = NTILE * 2 + 16;
    constexpr int CH = NTILE / 8;       // 16B chunks per row
#pragma unroll
    for (int i = 0; i < NTILE / 16; i++) {
        int id = tid + i * 128;
        int r = id / CH, q = id % CH;   // 64 k-rows x CH chunks
        CP_ASYNC16(sb + off + r * BROW + q * 16,
                   W + (size_t)(kc + r) * Ntot + n0 + q * 8);
    }
}

// MODE 0: L1  -> Ho=tanh(z+beff) bf16, Do=(1-h^2)*z1t bf16
// MODE 4: L2v -> h2=tanh(z+beff) bf16 -> O1
// MODE 5: L2t -> Trp[16 partials] = sum q*(1-h2^2)*z  (h2 read, mask inline fp32)
// MODE 1: L3  -> v=z+bias; RK4 Xeb/Xacc/Xt   (NTILE=64)
// MODE 2: precompute z1t/q bf16 (blockIdx.x<8 -> Wb/O1, else Wb2/O2), A fp32
template <int MODE, bool AFP32, int NTILE>
__global__ void __launch_bounds__(128, (NTILE == 64 ? 4 : 3))
gemm_bf16(const void* __restrict__ Avp,
          const __nv_bfloat16* __restrict__ Wb, const __nv_bfloat16* __restrict__ Wb2,
          const float* __restrict__ bias, const float* __restrict__ wt, float tval,
          int K, int Ntot,
          void* __restrict__ O1, void* __restrict__ O2,
          const __nv_bfloat16* __restrict__ Z1Tb,
          float* __restrict__ Trp, const __nv_bfloat16* __restrict__ Qb,
          const __nv_bfloat16* __restrict__ H2b,
          float* __restrict__ Xt, __nv_bfloat16* __restrict__ Xtb,
          __nv_bfloat16* __restrict__ Xeb, float* __restrict__ Xacc,
          float cEval, float wInt, int slot)
{
    constexpr int BROW = NTILE * 2 + 16;
    constexpr int BBYTES = 64 * BROW;
    constexpr int BUF = A_BYTES + BBYTES;
    constexpr int NI = NTILE / 16;      // 8-col groups per warp
    constexpr int NH = NI / 2;          // groups per half

    extern __shared__ char smem[];
    float* beff = (float*)smem;
    const uint32_t sb = smem_u32(smem);
    const int tid = threadIdx.x;
    const int lane = tid & 31, warp = tid >> 5;
    const int m0 = blockIdx.y * 128;
    const int n0 = (MODE == 2) ? (blockIdx.x & 7) * 128 : blockIdx.x * NTILE;
    const int wm = warp >> 1, wn = warp & 1;          // 2(M) x 2(N) warps

    const __nv_bfloat16* Wu = (MODE == 2 && blockIdx.x >= 8) ? Wb2 : Wb;

    if (MODE != 2 && MODE != 5 && tid < NTILE) {
        float be = bias[n0 + tid];
        if (MODE == 0 && wt) be += tval * wt[n0 + tid];
        beff[tid] = be;
    }

    float acc[4][NI][4];                              // 64(M) x NTILE/2 warp tile
#pragma unroll
    for (int mi = 0; mi < 4; mi++)
#pragma unroll
        for (int ni = 0; ni < NI; ni++)
#pragma unroll
            for (int e = 0; e < 4; e++) acc[mi][ni][e] = 0.f;

    const int NC = K / 64;

    // prologue: stage chunk 0 into buffer 0
    stage_A<AFP32>(sb, 512, Avp, K, m0, 0, tid);
    stage_B<NTILE>(sb, 512 + A_BYTES, Wu, Ntot, n0, 0, tid);
    CP_COMMIT();

    const int lrow = ((lane >> 3) & 1) * 8 + (lane & 7);   // ldmatrix x4 lane->row
    const int lcol = (lane >> 4) << 4;                     // ldmatrix x4 lane->16B col

    for (int c = 0; c < NC; c++) {
        const int b = c & 1;
        if (c + 1 < NC) {
            const int nb = (c + 1) & 1;
            stage_A<AFP32>(sb, 512 + nb * BUF, Avp, K, m0, (c + 1) * 64, tid);
            stage_B<NTILE>(sb, 512 + nb * BUF + A_BYTES, Wu, Ntot, n0, (c + 1) * 64, tid);
            CP_COMMIT();
            CP_WAIT(1);
        } else {
            CP_WAIT(0);
        }
        __syncthreads();

        const uint32_t aav = sb + 512 + b * BUF + (wm * 64 + lrow) * 144 + lcol;
        const uint32_t abT = sb + 512 + b * BUF + A_BYTES
                           + (lane & 15) * BROW + lcol + wn * NTILE;
#pragma unroll
        for (int kk = 0; kk < 4; kk++) {
            uint32_t av[4][4], bf[NH][2];
#pragma unroll
            for (int mi = 0; mi < 4; mi++)
                LDSM4(av[mi][0], av[mi][1], av[mi][2], av[mi][3],
                      aav + mi * 2304 + kk * 32);
            // B in two halves to cap live registers
#pragma unroll
            for (int h = 0; h < 2; h++) {
#pragma unroll
                for (int p = 0; p < NH / 2; p++)
                    LDSM4T(bf[2 * p][0], bf[2 * p][1], bf[2 * p + 1][0], bf[2 * p + 1][1],
                           abT + kk * 16 * BROW + h * (NTILE / 2) + p * 32);
#pragma unroll
                for (int mi = 0; mi < 4; mi++)
#pragma unroll
                    for (int nj = 0; nj < NH; nj++)
                        MMA16816(acc[mi][h * NH + nj], av[mi], bf[nj]);
            }
        }
        __syncthreads();
    }

    // ---------------- epilogue ----------------
    const int g = lane >> 2, tg = lane & 3;
    float trs[4][2] = {{0.f,0.f},{0.f,0.f},{0.f,0.f},{0.f,0.f}};
#pragma unroll
    for (int mi = 0; mi < 4; mi++)
#pragma unroll
        for (int ni = 0; ni < NI; ni++) {
            const int colp = wn * (NTILE / 2) + ni * 8 + 2 * tg;
            const int colg = n0 + colp;
#pragma unroll
            for (int rh = 0; rh < 2; rh++) {
                const int row = m0 + wm * 64 + mi * 16 + rh * 8 + g;
                const float z0 = acc[mi][ni][rh * 2 + 0];
                const float z1 = acc[mi][ni][rh * 2 + 1];
                if (MODE == 2) {
                    __nv_bfloat16* O = (blockIdx.x < 8) ? (__nv_bfloat16*)O1
                                                        : (__nv_bfloat16*)O2;
                    *(__nv_bfloat162*)(O + (size_t)row * Ntot + colg) =
                        __floats2bfloat162_rn(z0, z1);
                } else if (MODE == 0) {
                    const float h0 = tanh_fast(z0 + beff[colp]);
                    const float h1 = tanh_fast(z1 + beff[colp + 1]);
                    __nv_bfloat162 zt2 =
                        *(const __nv_bfloat162*)(Z1Tb + (size_t)row * Ntot + colg);
                    const float d0 = (1.f - h0 * h0) * __bfloat162float(zt2.x);
                    const float d1 = (1.f - h1 * h1) * __bfloat162float(zt2.y);
                    *(__nv_bfloat162*)((__nv_bfloat16*)O1 + (size_t)row * Ntot + colg) =
                        __floats2bfloat162_rn(h0, h1);
                    *(__nv_bfloat162*)((__nv_bfloat16*)O2 + (size_t)row * Ntot + colg) =
                        __floats2bfloat162_rn(d0, d1);
                } else if (MODE == 4) {
                    const float h0 = tanh_fast(z0 + beff[colp]);
                    const float h1 = tanh_fast(z1 + beff[colp + 1]);
                    *(__nv_bfloat162*)((__nv_bfloat16*)O1 + (size_t)row * Ntot + colg) =
                        __floats2bfloat162_rn(h0, h1);
                } else if (MODE == 5) {
                    __nv_bfloat162 hh =
                        *(const __nv_bfloat162*)(H2b + (size_t)row * Ntot + colg);
                    __nv_bfloat162 q2 =
                        *(const __nv_bfloat162*)(Qb + (size_t)row * Ntot + colg);
                    const float hx = __bfloat162float(hh.x);
                    const float hy = __bfloat162float(hh.y);
                    trs[mi][rh] += __bfloat162float(q2.x) * (1.f - hx * hx) * z0
                                 + __bfloat162float(q2.y) * (1.f - hy * hy) * z1;
                } else {  // MODE 1: L3 value + RK4 integration
                    const float v0 = z0 + beff[colp];
                    const float v1 = z1 + beff[colp + 1];
                    const size_t o = (size_t)row * 256 + colg;
                    if (slot == 0) {
                        float2 a2; a2.x = wInt * v0; a2.y = wInt * v1;
                        *(float2*)(Xacc + o) = a2;
                        float2 x2 = *(const float2*)(Xt + o);
                        *(__nv_bfloat162*)(Xeb + o) =
                            __floats2bfloat162_rn(x2.x + cEval * v0, x2.y + cEval * v1);
                    } else if (slot < 3) {
                        float2 a2 = *(const float2*)(Xacc + o);
                        a2.x += wInt * v0; a2.y += wInt * v1;
                        *(float2*)(Xacc + o) = a2;
                        float2 x2 = *(const float2*)(Xt + o);
                        *(__nv_bfloat162*)(Xeb + o) =
                            __floats2bfloat162_rn(x2.x + cEval * v0, x2.y + cEval * v1);
                    } else {
                        float2 a2 = *(const float2*)(Xacc + o);
                        float2 x2 = *(const float2*)(Xt + o);
                        x2.x += a2.x + wInt * v0;
                        x2.y += a2.y + wInt * v1;
                        *(float2*)(Xt + o) = x2;
                        *(__nv_bfloat162*)(Xtb + o) = __floats2bfloat162_rn(x2.x, x2.y);
                    }
                }
            }
        }
    if (MODE == 5) {
#pragma unroll
        for (int mi = 0; mi < 4; mi++)
#pragma unroll
            for (int rh = 0; rh < 2; rh++) {
                float s = trs[mi][rh];
                s += __shfl_xor_sync(0xffffffffu, s, 1);
                s += __shfl_xor_sync(0xffffffffu, s, 2);
                if (tg == 0) {
                    const int row = m0 + wm * 64 + mi * 16 + rh * 8 + g;
                    Trp[(size_t)(blockIdx.x * 2 + wn) * B_ + row] = s;
                }
            }
    }
}

// ---------------- one-shot prep: weight cvt + W3 transpose + state init ----------------
__global__ void __launch_bounds__(256)
prep_kernel(const float* __restrict__ x,
            const float* __restrict__ W1, const float* __restrict__ W2,
            const float* __restrict__ W3)
{
    int i = blockIdx.x * 256 + threadIdx.x;
    if (i < (D_ + 1) * H_) g_W1b[i] = __float2bfloat16(W1[i]);
    if (i < H_ * H_)       g_W2b[i] = __float2bfloat16(W2[i]);
    if (i < H_ * D_) {
        float w = W3[i];
        g_W3b[i] = __float2bfloat16(w);
        int r = i / D_, c = i % D_;
        g_W3Tb[(size_t)c * H_ + r] = __float2bfloat16(w);
    }
    if (i < B_ * D_) {
        float v = x[i];
        g_xt[i] = v;
        g_xtb[i] = __float2bfloat16(v);
    }
}

// ---------------- noise = sin(1000*(x@proj))*sqrt(2), plain fp32 ----------------
__global__ void __launch_bounds__(256)
noise_kernel(const float* __restrict__ X, const float* __restrict__ P)
{
    __shared__ float As[64][17];
    __shared__ float Bs[16][68];
    int bm = blockIdx.y * 64, bn = blockIdx.x * 64;
    int tx = threadIdx.x, ty = threadIdx.y;
    int tid = ty * 16 + tx;
    float acc[4][4];
#pragma unroll
    for (int i = 0; i < 4; i++)
#pragma unroll
        for (int j = 0; j < 4; j++) acc[i][j] = 0.f;

    for (int k0 = 0; k0 < D_; k0 += 16) {
        int ar = tid >> 2, ac = (tid & 3) * 4;
        float4 a4 = *(const float4*)(X + (size_t)(bm + ar) * D_ + k0 + ac);
        As[ar][ac + 0] = a4.x; As[ar][ac + 1] = a4.y; As[ar][ac + 2] = a4.z; As[ar][ac + 3] = a4.w;
        int br = tid >> 4, bc = (tid & 15) * 4;
        float4 b4 = *(const float4*)(P + (size_t)(k0 + br) * D_ + bn + bc);
        Bs[br][bc + 0] = b4.x; Bs[br][bc + 1] = b4.y; Bs[br][bc + 2] = b4.z; Bs[br][bc + 3] = b4.w;
        __syncthreads();
#pragma unroll
        for (int k = 0; k < 16; k++) {
            float a[4], b[4];
#pragma unroll
            for (int i = 0; i < 4; i++) a[i] = As[ty * 4 + i][k];
#pragma unroll
            for (int j = 0; j < 4; j++) b[j] = Bs[k][tx * 4 + j];
#pragma unroll
            for (int i = 0; i < 4; i++)
#pragma unroll
                for (int j = 0; j < 4; j++) acc[i][j] = fmaf(a[i], b[j], acc[i][j]);
        }
        __syncthreads();
    }
#pragma unroll
    for (int i = 0; i < 4; i++)
#pragma unroll
        for (int j = 0; j < 4; j++)
            g_noise[(size_t)(bm + ty * 4 + i) * D_ + bn + tx * 4 + j] =
                sinf(1000.f * acc[i][j]) * 1.41421356f;
}

// ---------------- final: fold ALL trace partials + log-prob ----------------
__global__ void __launch_bounds__(256)
final_kernel(float* __restrict__ out, float w6)
{
    __shared__ float ljs[256];
    const int r0 = blockIdx.x * 256;
    const int tid = threadIdx.x;
    {
        const int row = r0 + tid;
        float lj = 0.f;
        for (int s = 0; s < 40; s++) {
            float t = 0.f;
#pragma unroll
            for (int p = 0; p < 16; p++) t += g_trp[s][p][row];
            const int sm = s & 3;
            const float c = (sm == 0 || sm == 3) ? w6 : 2.f * w6;
            lj += c * t;
        }
        ljs[tid] = lj;
    }
    __syncthreads();
    const int warp = tid >> 5, lane = tid & 31;
    for (int i = warp; i < 256; i += 8) {
        const int row = r0 + i;
        const float* xr = g_xt + (size_t)row * D_;
        float s = 0.f;
#pragma unroll
        for (int c = 0; c < D_; c += 32) { float v = xr[c + lane]; s += v * v; }
#pragma unroll
        for (int o = 16; o > 0; o >>= 1) s += __shfl_xor_sync(0xffffffffu, s, o);
        if (lane == 0) out[row] = -0.5f * s - 235.2482645f - ljs[i];
    }
}

// ---------------- launch ----------------
extern "C" void kernel_launch(void* const* d_in, const int* in_sizes, int n_in,
                              void* d_out, int out_size)
{
    const float* x  = (const float*)d_in[0];
    const float* W1 = (const float*)d_in[1];
    const float* b1 = (const float*)d_in[2];
    const float* W2 = (const float*)d_in[3];
    const float* b2 = (const float*)d_in[4];
    const float* W3 = (const float*)d_in[5];
    const float* b3 = (const float*)d_in[6];
    const float* pj = (const float*)d_in[7];
    float* out = (float*)d_out;

    constexpr int SMEM128 = 512 + 2 * (A_BYTES + 64 * 272);   // 72,192
    constexpr int SMEM64  = 512 + 2 * (A_BYTES + 64 * 144);   // 55,808

    float *noise, *trbase, *xt, *xacc;
    __nv_bfloat16 *z1tb, *qb, *h1b, *dh1b, *h2b, *w1b, *w2b, *w3b, *w3tb, *xtb, *xeb;
    cudaGetSymbolAddress((void**)&noise,  g_noise);
    cudaGetSymbolAddress((void**)&z1tb,   g_z1tb);
    cudaGetSymbolAddress((void**)&qb,     g_qb);
    cudaGetSymbolAddress((void**)&h1b,    g_h1b);
    cudaGetSymbolAddress((void**)&dh1b,   g_dh1b);
    cudaGetSymbolAddress((void**)&h2b,    g_h2b);
    cudaGetSymbolAddress((void**)&w1b,    g_W1b);
    cudaGetSymbolAddress((void**)&w2b,    g_W2b);
    cudaGetSymbolAddress((void**)&w3b,    g_W3b);
    cudaGetSymbolAddress((void**)&w3tb,   g_W3Tb);
    cudaGetSymbolAddress((void**)&trbase, g_trp);
    cudaGetSymbolAddress((void**)&xt,     g_xt);
    cudaGetSymbolAddress((void**)&xtb,    g_xtb);
    cudaGetSymbolAddress((void**)&xeb,    g_xeb);
    cudaGetSymbolAddress((void**)&xacc,   g_xacc);

    cudaFuncSetAttribute(gemm_bf16<0, false, 128>, cudaFuncAttributeMaxDynamicSharedMemorySize, SMEM128);
    cudaFuncSetAttribute(gemm_bf16<4, false, 128>, cudaFuncAttributeMaxDynamicSharedMemorySize, SMEM128);
    cudaFuncSetAttribute(gemm_bf16<5, false, 128>, cudaFuncAttributeMaxDynamicSharedMemorySize, SMEM128);
    cudaFuncSetAttribute(gemm_bf16<1, false, 64>,  cudaFuncAttributeMaxDynamicSharedMemorySize, SMEM64);
    cudaFuncSetAttribute(gemm_bf16<2, true, 128>,  cudaFuncAttributeMaxDynamicSharedMemorySize, SMEM128);

    // streams (high-priority critical path, low-priority tangent) + events
    static cudaStream_t s0 = nullptr, s1 = nullptr;
    static cudaEvent_t evA[40], evT[40], evRoot, evDone;
    if (s0 == nullptr) {
        int loP, hiP;
        cudaDeviceGetStreamPriorityRange(&loP, &hiP);
        cudaStreamCreateWithPriority(&s0, cudaStreamNonBlocking, hiP);
        cudaStreamCreateWithPriority(&s1, cudaStreamNonBlocking, loP);
        for (int i = 0; i < 40; i++) {
            cudaEventCreateWithFlags(&evA[i], cudaEventDisableTiming);
            cudaEventCreateWithFlags(&evT[i], cudaEventDisableTiming);
        }
        cudaEventCreateWithFlags(&evRoot, cudaEventDisableTiming);
        cudaEventCreateWithFlags(&evDone, cudaEventDisableTiming);
    }

    // fork from capture stream
    cudaEventRecord(evRoot, (cudaStream_t)0);
    cudaStreamWaitEvent(s0, evRoot, 0);

    prep_kernel<<<(B_ * D_) / 256, 256, 0, s0>>>(x, W1, W2, W3);
    noise_kernel<<<dim3(D_ / 64, B_ / 64), dim3(16, 16), 0, s0>>>(x, pj);
    gemm_bf16<2, true, 128><<<dim3(16, B_ / 128), 128, SMEM128, s0>>>(
        noise, w1b, w3tb, nullptr, nullptr, 0.f, D_, H_,
        z1tb, qb, nullptr, nullptr, nullptr, nullptr,
        nullptr, nullptr, nullptr, nullptr, 0.f, 0.f, 0);

    dim3 gridH(H_ / 128, B_ / 128);   // 8 x 128
    dim3 gridD(D_ / 64, B_ / 128);    // 4 x 128 = 512 CTAs (N=64 tiles)

    const float dt = -0.1f;
    const float w6 = dt / 6.f;
    const float wInt[4] = { w6, 2.f * w6, 2.f * w6, w6 };
    for (int k = 0; k < 10; k++) {
        float t = 1.0f + dt * (float)k;
        const float tts[4]  = { t, t + dt * 0.5f, t + dt * 0.5f, t + dt };
        const float cevs[4] = { dt * 0.5f, dt * 0.5f, dt, 0.f };
        for (int d = 0; d < 4; d++) {
            const int e = k * 4 + d;
            const int par = e & 3;
            __nv_bfloat16* dh1p = dh1b + (size_t)par * B_ * H_;
            __nv_bfloat16* h2p  = h2b  + (size_t)par * B_ * H_;
            const __nv_bfloat16* xin = (d == 0) ? xtb : xeb;

            // guard WAR on dh1b[par]/h2b[par] against in-flight L2t(e-4)
            if (e >= 4) cudaStreamWaitEvent(s0, evT[e - 4], 0);

            // L1: h1, dh1[par]
            gemm_bf16<0, false, 128><<<gridH, 128, SMEM128, s0>>>(
                xin, w1b, nullptr, b1, W1 + 256 * H_, tts[d], D_, H_,
                h1b, dh1p, z1tb, nullptr, nullptr, nullptr,
                nullptr, nullptr, nullptr, nullptr, 0.f, 0.f, 0);
            // L2 value: h2[par]
            gemm_bf16<4, false, 128><<<gridH, 128, SMEM128, s0>>>(
                h1b, w2b, nullptr, b2, nullptr, 0.f, H_, H_,
                h2p, nullptr, nullptr, nullptr, nullptr, nullptr,
                nullptr, nullptr, nullptr, nullptr, 0.f, 0.f, 0);

            // fork: L2 tangent on low-priority s1 (independent of L3)
            cudaEventRecord(evA[e], s0);
            cudaStreamWaitEvent(s1, evA[e], 0);
            gemm_bf16<5, false, 128><<<gridH, 128, SMEM128, s1>>>(
                dh1p, w2b, nullptr, nullptr, nullptr, 0.f, H_, H_,
                nullptr, nullptr, nullptr,
                trbase + (size_t)e * 16 * B_, qb, h2p,
                nullptr, nullptr, nullptr, nullptr, 0.f, 0.f, 0);
            cudaEventRecord(evT[e], s1);

            // L3: value + RK4 (high-priority stream, overlaps L2t)
            gemm_bf16<1, false, 64><<<gridD, 128, SMEM64, s0>>>(
                h2p, w3b, nullptr, b3, nullptr, 0.f, H_, D_,
                nullptr, nullptr, nullptr, nullptr, nullptr, nullptr,
                xt, xtb, xeb, xacc, cevs[d], wInt[d], d);
        }
    }
    // join: all trace partials final before fold
    cudaStreamWaitEvent(s0, evT[38], 0);
    cudaStreamWaitEvent(s0, evT[39], 0);
    final_kernel<<<B_ / 256, 256, 0, s0>>>(out, w6);

    // join back to capture stream
    cudaEventRecord(evDone, s0);
    cudaStreamWaitEvent((cudaStream_t)0, evDone, 0);
}

// round 15
// speedup vs baseline: 1.1027x; 1.1027x over previous
#include <cuda_runtime.h>
#include <cuda_bf16.h>
#include <cstdint>
#include <cstddef>

#define B_ 16384
#define D_ 256
#define H_ 1024

// ---------------- scratch (device globals: no allocation allowed) ----------------
__device__ float g_noise[B_ * D_];
__device__ __nv_bfloat16 g_z1tb[B_ * H_];
__device__ __nv_bfloat16 g_qb[B_ * H_];
__device__ __nv_bfloat16 g_h1b[B_ * H_];
__device__ __nv_bfloat16 g_dh1b[2][B_ * H_];
__device__ __nv_bfloat16 g_h2b[2][B_ * H_];
__device__ __nv_bfloat16 g_W1b[(D_ + 1) * H_];
__device__ __nv_bfloat16 g_W2b[H_ * H_];
__device__ __nv_bfloat16 g_W3b[H_ * D_];
__device__ __nv_bfloat16 g_W3Tb[D_ * H_];
__device__ float g_trp[40][16][B_];
__device__ float g_xt[B_ * D_];
__device__ __nv_bfloat16 g_xtb[B_ * D_];
__device__ __nv_bfloat16 g_xeb[B_ * D_];
__device__ float g_xacc[B_ * D_];

// ---------------- PTX helpers ----------------
__device__ __forceinline__ uint32_t smem_u32(const void* p) {
    uint32_t a;
    asm("{ .reg .u64 t; cvta.to.shared.u64 t, %1; cvt.u32.u64 %0, t; }" : "=r"(a) : "l"(p));
    return a;
}

__device__ __forceinline__ float tanh_fast(float x) {
    float y;
    asm("tanh.approx.f32 %0, %1;" : "=f"(y) : "f"(x));
    return y;
}

#define CP_ASYNC16(dst, src) \
    asm volatile("cp.async.cg.shared.global [%0], [%1], 16;" :: "r"(dst), "l"(src) : "memory")
#define CP_COMMIT() asm volatile("cp.async.commit_group;" ::: "memory")
#define CP_WAIT(n)  asm volatile("cp.async.wait_group %0;" :: "n"(n) : "memory")

#define LDSM4(r0, r1, r2, r3, a) \
    asm volatile("ldmatrix.sync.aligned.m8n8.x4.shared.b16 {%0,%1,%2,%3}, [%4];" \
        : "=r"(r0), "=r"(r1), "=r"(r2), "=r"(r3) : "r"(a))
#define LDSM4T(r0, r1, r2, r3, a) \
    asm volatile("ldmatrix.sync.aligned.m8n8.x4.trans.shared.b16 {%0,%1,%2,%3}, [%4];" \
        : "=r"(r0), "=r"(r1), "=r"(r2), "=r"(r3) : "r"(a))

#define MMA16816(d, a, b) \
    asm volatile("mma.sync.aligned.m16n8k16.row.col.f32.bf16.bf16.f32 " \
        "{%0,%1,%2,%3}, {%4,%5,%6,%7}, {%8,%9}, {%0,%1,%2,%3};" \
        : "+f"((d)[0]), "+f"((d)[1]), "+f"((d)[2]), "+f"((d)[3]) \
        : "r"((a)[0]), "r"((a)[1]), "r"((a)[2]), "r"((a)[3]), "r"((b)[0]), "r"((b)[1]))

// ---------------- tiling (R10/R13-proven) ----------------
// CTA: 128 threads (4 warps, 2(M) x 2(N)); CTA tile M=128, N=128; warp tile 64x64.
// K-chunk 64, 2-stage pipeline. 3 CTA/SM.
#define A_BYTES   18432          // 128 rows x 144
#define B_BYTES   17408          // 64 rows x 272
#define BUF_S     (A_BYTES + B_BYTES)
#define OFF_AV(b) (512 + (b) * BUF_S)
#define OFF_BB(b) (OFF_AV(b) + A_BYTES)
#define SMEM_SZ   (512 + 2 * BUF_S)

template <bool AFP32>
__device__ __forceinline__ void stage_A(uint32_t sb, int off, const void* Ap,
                                        int K, int m0, int kc, int tid)
{
    if (AFP32) {
        const float* A = (const float*)Ap;
#pragma unroll
        for (int i = 0; i < 8; i++) {
            int id = tid + i * 128;
            int r = id >> 3, q = id & 7;
            const float* s = A + (size_t)(m0 + r) * K + kc + q * 8;
            float4 u = *(const float4*)s;
            float4 v = *(const float4*)(s + 4);
            __nv_bfloat162 p0 = __floats2bfloat162_rn(u.x, u.y);
            __nv_bfloat162 p1 = __floats2bfloat162_rn(u.z, u.w);
            __nv_bfloat162 p2 = __floats2bfloat162_rn(v.x, v.y);
            __nv_bfloat162 p3 = __floats2bfloat162_rn(v.z, v.w);
            uint32_t d = sb + off + r * 144 + q * 16;
            asm volatile("st.shared.v4.b32 [%0], {%1,%2,%3,%4};" :: "r"(d),
                "r"(*(uint32_t*)&p0), "r"(*(uint32_t*)&p1),
                "r"(*(uint32_t*)&p2), "r"(*(uint32_t*)&p3) : "memory");
        }
    } else {
        const __nv_bfloat16* A = (const __nv_bfloat16*)Ap;
#pragma unroll
        for (int i = 0; i < 8; i++) {
            int id = tid + i * 128;
            int r = id >> 3, q = id & 7;
            CP_ASYNC16(sb + off + r * 144 + q * 16,
                       A + (size_t)(m0 + r) * K + kc + q * 8);
        }
    }
}

__device__ __forceinline__ void stage_B(uint32_t sb, int off, const __nv_bfloat16* W,
                                        int Ntot, int n0, int kc, int tid)
{
#pragma unroll
    for (int i = 0; i < 8; i++) {
        int id = tid + i * 128;
        int r = id >> 4, q = id & 15;   // 64 k-rows x 16 x 16B chunks (128 cols)
        CP_ASYNC16(sb + off + r * 272 + q * 16,
                   W + (size_t)(kc + r) * Ntot + n0 + q * 8);
    }
}

// MODE 0: L1  -> Ho=tanh(z+beff) bf16, Do=(1-h^2)*z1t bf16
// MODE 4: L2v -> h2=tanh(z+beff) bf16 -> O1   (m2 not stored)
// MODE 5: L2t -> Trp[16 partials] = sum q*(1-h2^2)*z  (h2 read, mask inline fp32)
// MODE 1: L3  -> v=z+bias; RK4 Xeb/Xacc/Xt
// MODE 2: precompute z1t/q bf16 (blockIdx.x<8 -> Wb/O1, else Wb2/O2), A fp32
template <int MODE, bool AFP32>
__global__ void __launch_bounds__(128, 3)
gemm_bf16(const void* __restrict__ Avp,
          const __nv_bfloat16* __restrict__ Wb, const __nv_bfloat16* __restrict__ Wb2,
          const float* __restrict__ bias, const float* __restrict__ wt, float tval,
          int K, int Ntot,
          void* __restrict__ O1, void* __restrict__ O2,
          const __nv_bfloat16* __restrict__ Z1Tb,
          float* __restrict__ Trp, const __nv_bfloat16* __restrict__ Qb,
          const __nv_bfloat16* __restrict__ H2b,
          float* __restrict__ Xt, __nv_bfloat16* __restrict__ Xtb,
          __nv_bfloat16* __restrict__ Xeb, float* __restrict__ Xacc,
          float cEval, float wInt, int slot)
{
    extern __shared__ char smem[];
    float* beff = (float*)smem;
    const uint32_t sb = smem_u32(smem);
    const int tid = threadIdx.x;
    const int lane = tid & 31, warp = tid >> 5;
    const int m0 = blockIdx.y * 128;
    const int n0 = (MODE == 2) ? (blockIdx.x & 7) * 128 : blockIdx.x * 128;
    const int wm = warp >> 1, wn = warp & 1;          // 2(M) x 2(N) warps

    const __nv_bfloat16* Wu = (MODE == 2 && blockIdx.x >= 8) ? Wb2 : Wb;

    if (MODE != 2 && MODE != 5) {
        float be = bias[n0 + tid];
        if (MODE == 0 && wt) be += tval * wt[n0 + tid];
        beff[tid] = be;
    }

    float acc[4][8][4];                               // 64(M) x 64(N) warp tile
#pragma unroll
    for (int mi = 0; mi < 4; mi++)
#pragma unroll
        for (int ni = 0; ni < 8; ni++)
#pragma unroll
            for (int e = 0; e < 4; e++) acc[mi][ni][e] = 0.f;

    const int NC = K / 64;

    // prologue: stage chunk 0 into buffer 0
    stage_A<AFP32>(sb, OFF_AV(0), Avp, K, m0, 0, tid);
    stage_B(sb, OFF_BB(0), Wu, Ntot, n0, 0, tid);
    CP_COMMIT();

    const int lrow = ((lane >> 3) & 1) * 8 + (lane & 7);   // ldmatrix x4 lane->row
    const int lcol = (lane >> 4) << 4;                     // ldmatrix x4 lane->16B col

    for (int c = 0; c < NC; c++) {
        const int b = c & 1;
        if (c + 1 < NC) {
            const int nb = (c + 1) & 1;
            stage_A<AFP32>(sb, OFF_AV(nb), Avp, K, m0, (c + 1) * 64, tid);
            stage_B(sb, OFF_BB(nb), Wu, Ntot, n0, (c + 1) * 64, tid);
            CP_COMMIT();
            CP_WAIT(1);
        } else {
            CP_WAIT(0);
        }
        __syncthreads();

        const uint32_t aav = sb + OFF_AV(b) + (wm * 64 + lrow) * 144 + lcol;
        const uint32_t abT = sb + OFF_BB(b) + (lane & 15) * 272 + lcol + wn * 128;
#pragma unroll
        for (int kk = 0; kk < 4; kk++) {
            uint32_t av[4][4], bf[4][2];
#pragma unroll
            for (int mi = 0; mi < 4; mi++)
                LDSM4(av[mi][0], av[mi][1], av[mi][2], av[mi][3],
                      aav + mi * 2304 + kk * 32);
            // B in two halves to cap live registers
#pragma unroll
            for (int h = 0; h < 2; h++) {
#pragma unroll
                for (int p = 0; p < 2; p++)
                    LDSM4T(bf[2 * p][0], bf[2 * p][1], bf[2 * p + 1][0], bf[2 * p + 1][1],
                           abT + kk * 4352 + h * 64 + p * 32);
#pragma unroll
                for (int mi = 0; mi < 4; mi++)
#pragma unroll
                    for (int nj = 0; nj < 4; nj++)
                        MMA16816(acc[mi][h * 4 + nj], av[mi], bf[nj]);
            }
        }
        __syncthreads();
    }

    // ---------------- epilogue ----------------
    const int g = lane >> 2, tg = lane & 3;
    float trs[4][2] = {{0.f,0.f},{0.f,0.f},{0.f,0.f},{0.f,0.f}};
#pragma unroll
    for (int mi = 0; mi < 4; mi++)
#pragma unroll
        for (int ni = 0; ni < 8; ni++) {
            const int colp = wn * 64 + ni * 8 + 2 * tg;
            const int colg = n0 + colp;
#pragma unroll
            for (int rh = 0; rh < 2; rh++) {
                const int row = m0 + wm * 64 + mi * 16 + rh * 8 + g;
                const float z0 = acc[mi][ni][rh * 2 + 0];
                const float z1 = acc[mi][ni][rh * 2 + 1];
                if (MODE == 2) {
                    __nv_bfloat16* O = (blockIdx.x < 8) ? (__nv_bfloat16*)O1
                                                        : (__nv_bfloat16*)O2;
                    *(__nv_bfloat162*)(O + (size_t)row * Ntot + colg) =
                        __floats2bfloat162_rn(z0, z1);
                } else if (MODE == 0) {
                    const float h0 = tanh_fast(z0 + beff[colp]);
                    const float h1 = tanh_fast(z1 + beff[colp + 1]);
                    __nv_bfloat162 zt2 =
                        *(const __nv_bfloat162*)(Z1Tb + (size_t)row * Ntot + colg);
                    const float d0 = (1.f - h0 * h0) * __bfloat162float(zt2.x);
                    const float d1 = (1.f - h1 * h1) * __bfloat162float(zt2.y);
                    *(__nv_bfloat162*)((__nv_bfloat16*)O1 + (size_t)row * Ntot + colg) =
                        __floats2bfloat162_rn(h0, h1);
                    *(__nv_bfloat162*)((__nv_bfloat16*)O2 + (size_t)row * Ntot + colg) =
                        __floats2bfloat162_rn(d0, d1);
                } else if (MODE == 4) {
                    const float h0 = tanh_fast(z0 + beff[colp]);
                    const float h1 = tanh_fast(z1 + beff[colp + 1]);
                    *(__nv_bfloat162*)((__nv_bfloat16*)O1 + (size_t)row * Ntot + colg) =
                        __floats2bfloat162_rn(h0, h1);
                } else if (MODE == 5) {
                    __nv_bfloat162 hh =
                        *(const __nv_bfloat162*)(H2b + (size_t)row * Ntot + colg);
                    __nv_bfloat162 q2 =
                        *(const __nv_bfloat162*)(Qb + (size_t)row * Ntot + colg);
                    const float hx = __bfloat162float(hh.x);
                    const float hy = __bfloat162float(hh.y);
                    trs[mi][rh] += __bfloat162float(q2.x) * (1.f - hx * hx) * z0
                                 + __bfloat162float(q2.y) * (1.f - hy * hy) * z1;
                } else {  // MODE 1: L3 value + RK4 integration
                    const float v0 = z0 + beff[colp];
                    const float v1 = z1 + beff[colp + 1];
                    const size_t o = (size_t)row * 256 + colg;
                    if (slot == 0) {
                        float2 a2; a2.x = wInt * v0; a2.y = wInt * v1;
                        *(float2*)(Xacc + o) = a2;
                        float2 x2 = *(const float2*)(Xt + o);
                        *(__nv_bfloat162*)(Xeb + o) =
                            __floats2bfloat162_rn(x2.x + cEval * v0, x2.y + cEval * v1);
                    } else if (slot < 3) {
                        float2 a2 = *(const float2*)(Xacc + o);
                        a2.x += wInt * v0; a2.y += wInt * v1;
                        *(float2*)(Xacc + o) = a2;
                        float2 x2 = *(const float2*)(Xt + o);
                        *(__nv_bfloat162*)(Xeb + o) =
                            __floats2bfloat162_rn(x2.x + cEval * v0, x2.y + cEval * v1);
                    } else {
                        float2 a2 = *(const float2*)(Xacc + o);
                        float2 x2 = *(const float2*)(Xt + o);
                        x2.x += a2.x + wInt * v0;
                        x2.y += a2.y + wInt * v1;
                        *(float2*)(Xt + o) = x2;
                        *(__nv_bfloat162*)(Xtb + o) = __floats2bfloat162_rn(x2.x, x2.y);
                    }
                }
            }
        }
    if (MODE == 5) {
#pragma unroll
        for (int mi = 0; mi < 4; mi++)
#pragma unroll
            for (int rh = 0; rh < 2; rh++) {
                float s = trs[mi][rh];
                s += __shfl_xor_sync(0xffffffffu, s, 1);
                s += __shfl_xor_sync(0xffffffffu, s, 2);
                if (tg == 0) {
                    const int row = m0 + wm * 64 + mi * 16 + rh * 8 + g;
                    Trp[(size_t)(blockIdx.x * 2 + wn) * B_ + row] = s;
                }
            }
    }
}

// ---------------- one-shot prep: weight cvt + W3 transpose + state init ----------------
__global__ void __launch_bounds__(256)
prep_kernel(const float* __restrict__ x,
            const float* __restrict__ W1, const float* __restrict__ W2,
            const float* __restrict__ W3)
{
    int i = blockIdx.x * 256 + threadIdx.x;
    if (i < (D_ + 1) * H_) g_W1b[i] = __float2bfloat16(W1[i]);
    if (i < H_ * H_)       g_W2b[i] = __float2bfloat16(W2[i]);
    if (i < H_ * D_) {
        float w = W3[i];
        g_W3b[i] = __float2bfloat16(w);
        int r = i / D_, c = i % D_;
        g_W3Tb[(size_t)c * H_ + r] = __float2bfloat16(w);
    }
    if (i < B_ * D_) {
        float v = x[i];
        g_xt[i] = v;
        g_xtb[i] = __float2bfloat16(v);
    }
}

// ---------------- noise = sin(1000*(x@proj))*sqrt(2), plain fp32 ----------------
__global__ void __launch_bounds__(256)
noise_kernel(const float* __restrict__ X, const float* __restrict__ P)
{
    __shared__ float As[64][17];
    __shared__ float Bs[16][68];
    int bm = blockIdx.y * 64, bn = blockIdx.x * 64;
    int tx = threadIdx.x, ty = threadIdx.y;
    int tid = ty * 16 + tx;
    float acc[4][4];
#pragma unroll
    for (int i = 0; i < 4; i++)
#pragma unroll
        for (int j = 0; j < 4; j++) acc[i][j] = 0.f;

    for (int k0 = 0; k0 < D_; k0 += 16) {
        int ar = tid >> 2, ac = (tid & 3) * 4;
        float4 a4 = *(const float4*)(X + (size_t)(bm + ar) * D_ + k0 + ac);
        As[ar][ac + 0] = a4.x; As[ar][ac + 1] = a4.y; As[ar][ac + 2] = a4.z; As[ar][ac + 3] = a4.w;
        int br = tid >> 4, bc = (tid & 15) * 4;
        float4 b4 = *(const float4*)(P + (size_t)(k0 + br) * D_ + bn + bc);
        Bs[br][bc + 0] = b4.x; Bs[br][bc + 1] = b4.y; Bs[br][bc + 2] = b4.z; Bs[br][bc + 3] = b4.w;
        __syncthreads();
#pragma unroll
        for (int k = 0; k < 16; k++) {
            float a[4], b[4];
#pragma unroll
            for (int i = 0; i < 4; i++) a[i] = As[ty * 4 + i][k];
#pragma unroll
            for (int j = 0; j < 4; j++) b[j] = Bs[k][tx * 4 + j];
#pragma unroll
            for (int i = 0; i < 4; i++)
#pragma unroll
                for (int j = 0; j < 4; j++) acc[i][j] = fmaf(a[i], b[j], acc[i][j]);
        }
        __syncthreads();
    }
#pragma unroll
    for (int i = 0; i < 4; i++)
#pragma unroll
        for (int j = 0; j < 4; j++)
            g_noise[(size_t)(bm + ty * 4 + i) * D_ + bn + tx * 4 + j] =
                sinf(1000.f * acc[i][j]) * 1.41421356f;
}

// ---------------- final: fold ALL trace partials + log-prob ----------------
__global__ void __launch_bounds__(256)
final_kernel(float* __restrict__ out, float w6)
{
    __shared__ float ljs[256];
    const int r0 = blockIdx.x * 256;
    const int tid = threadIdx.x;
    {
        const int row = r0 + tid;
        float lj = 0.f;
        for (int s = 0; s < 40; s++) {
            float t = 0.f;
#pragma unroll
            for (int p = 0; p < 16; p++) t += g_trp[s][p][row];
            const int sm = s & 3;
            const float c = (sm == 0 || sm == 3) ? w6 : 2.f * w6;
            lj += c * t;
        }
        ljs[tid] = lj;
    }
    __syncthreads();
    const int warp = tid >> 5, lane = tid & 31;
    for (int i = warp; i < 256; i += 8) {
        const int row = r0 + i;
        const float* xr = g_xt + (size_t)row * D_;
        float s = 0.f;
#pragma unroll
        for (int c = 0; c < D_; c += 32) { float v = xr[c + lane]; s += v * v; }
#pragma unroll
        for (int o = 16; o > 0; o >>= 1) s += __shfl_xor_sync(0xffffffffu, s, o);
        if (lane == 0) out[row] = -0.5f * s - 235.2482645f - ljs[i];
    }
}

// ---------------- launch ----------------
extern "C" void kernel_launch(void* const* d_in, const int* in_sizes, int n_in,
                              void* d_out, int out_size)
{
    const float* x  = (const float*)d_in[0];
    const float* W1 = (const float*)d_in[1];
    const float* b1 = (const float*)d_in[2];
    const float* W2 = (const float*)d_in[3];
    const float* b2 = (const float*)d_in[4];
    const float* W3 = (const float*)d_in[5];
    const float* b3 = (const float*)d_in[6];
    const float* pj = (const float*)d_in[7];
    float* out = (float*)d_out;

    float *noise, *trbase, *xt, *xacc;
    __nv_bfloat16 *z1tb, *qb, *h1b, *dh1b, *h2b, *w1b, *w2b, *w3b, *w3tb, *xtb, *xeb;
    cudaGetSymbolAddress((void**)&noise,  g_noise);
    cudaGetSymbolAddress((void**)&z1tb,   g_z1tb);
    cudaGetSymbolAddress((void**)&qb,     g_qb);
    cudaGetSymbolAddress((void**)&h1b,    g_h1b);
    cudaGetSymbolAddress((void**)&dh1b,   g_dh1b);
    cudaGetSymbolAddress((void**)&h2b,    g_h2b);
    cudaGetSymbolAddress((void**)&w1b,    g_W1b);
    cudaGetSymbolAddress((void**)&w2b,    g_W2b);
    cudaGetSymbolAddress((void**)&w3b,    g_W3b);
    cudaGetSymbolAddress((void**)&w3tb,   g_W3Tb);
    cudaGetSymbolAddress((void**)&trbase, g_trp);
    cudaGetSymbolAddress((void**)&xt,     g_xt);
    cudaGetSymbolAddress((void**)&xtb,    g_xtb);
    cudaGetSymbolAddress((void**)&xeb,    g_xeb);
    cudaGetSymbolAddress((void**)&xacc,   g_xacc);

    cudaFuncSetAttribute(gemm_bf16<0, false>, cudaFuncAttributeMaxDynamicSharedMemorySize, SMEM_SZ);
    cudaFuncSetAttribute(gemm_bf16<4, false>, cudaFuncAttributeMaxDynamicSharedMemorySize, SMEM_SZ);
    cudaFuncSetAttribute(gemm_bf16<5, false>, cudaFuncAttributeMaxDynamicSharedMemorySize, SMEM_SZ);
    cudaFuncSetAttribute(gemm_bf16<1, false>, cudaFuncAttributeMaxDynamicSharedMemorySize, SMEM_SZ);
    cudaFuncSetAttribute(gemm_bf16<2, true>,  cudaFuncAttributeMaxDynamicSharedMemorySize, SMEM_SZ);

    // streams (high-priority critical path, low-priority tangent) + events
    static cudaStream_t s0 = nullptr, s1 = nullptr;
    static cudaEvent_t evA[40], evT[40], evRoot, evDone, evNz;
    if (s0 == nullptr) {
        int loP, hiP;
        cudaDeviceGetStreamPriorityRange(&loP, &hiP);
        cudaStreamCreateWithPriority(&s0, cudaStreamNonBlocking, hiP);
        cudaStreamCreateWithPriority(&s1, cudaStreamNonBlocking, loP);
        for (int i = 0; i < 40; i++) {
            cudaEventCreateWithFlags(&evA[i], cudaEventDisableTiming);
            cudaEventCreateWithFlags(&evT[i], cudaEventDisableTiming);
        }
        cudaEventCreateWithFlags(&evRoot, cudaEventDisableTiming);
        cudaEventCreateWithFlags(&evDone, cudaEventDisableTiming);
        cudaEventCreateWithFlags(&evNz,   cudaEventDisableTiming);
    }

    // fork from capture stream
    cudaEventRecord(evRoot, (cudaStream_t)0);
    cudaStreamWaitEvent(s0, evRoot, 0);
    cudaStreamWaitEvent(s1, evRoot, 0);

    // prologue fork: prep (s0) || noise (s1) — independent; join before z1t/q
    prep_kernel<<<(B_ * D_) / 256, 256, 0, s0>>>(x, W1, W2, W3);
    noise_kernel<<<dim3(D_ / 64, B_ / 64), dim3(16, 16), 0, s1>>>(x, pj);
    cudaEventRecord(evNz, s1);
    cudaStreamWaitEvent(s0, evNz, 0);
    gemm_bf16<2, true><<<dim3(16, B_ / 128), 128, SMEM_SZ, s0>>>(
        noise, w1b, w3tb, nullptr, nullptr, 0.f, D_, H_,
        z1tb, qb, nullptr, nullptr, nullptr, nullptr,
        nullptr, nullptr, nullptr, nullptr, 0.f, 0.f, 0);

    dim3 gridH(H_ / 128, B_ / 128);   // 8 x 128
    dim3 gridD(D_ / 128, B_ / 128);   // 2 x 128 = 256 CTAs

    const float dt = -0.1f;
    const float w6 = dt / 6.f;
    const float wInt[4] = { w6, 2.f * w6, 2.f * w6, w6 };
    for (int k = 0; k < 10; k++) {
        float t = 1.0f + dt * (float)k;
        const float tts[4]  = { t, t + dt * 0.5f, t + dt * 0.5f, t + dt };
        const float cevs[4] = { dt * 0.5f, dt * 0.5f, dt, 0.f };
        for (int d = 0; d < 4; d++) {
            const int e = k * 4 + d;
            const int par = e & 1;
            __nv_bfloat16* dh1p = dh1b + (size_t)par * B_ * H_;
            __nv_bfloat16* h2p  = h2b  + (size_t)par * B_ * H_;
            const __nv_bfloat16* xin = (d == 0) ? xtb : xeb;

            // guard WAR on dh1b[par]/h2b[par] against in-flight L2t(e-2)
            if (e >= 2) cudaStreamWaitEvent(s0, evT[e - 2], 0);

            // L1: h1, dh1[par]
            gemm_bf16<0, false><<<gridH, 128, SMEM_SZ, s0>>>(
                xin, w1b, nullptr, b1, W1 + 256 * H_, tts[d], D_, H_,
                h1b, dh1p, z1tb, nullptr, nullptr, nullptr,
                nullptr, nullptr, nullptr, nullptr, 0.f, 0.f, 0);
            // L2 value: h2[par]
            gemm_bf16<4, false><<<gridH, 128, SMEM_SZ, s0>>>(
                h1b, w2b, nullptr, b2, nullptr, 0.f, H_, H_,
                h2p, nullptr, nullptr, nullptr, nullptr, nullptr,
                nullptr, nullptr, nullptr, nullptr, 0.f, 0.f, 0);

            // fork: L2 tangent on low-priority s1 (independent of L3)
            cudaEventRecord(evA[e], s0);
            cudaStreamWaitEvent(s1, evA[e], 0);
            gemm_bf16<5, false><<<gridH, 128, SMEM_SZ, s1>>>(
                dh1p, w2b, nullptr, nullptr, nullptr, 0.f, H_, H_,
                nullptr, nullptr, nullptr,
                trbase + (size_t)e * 16 * B_, qb, h2p,
                nullptr, nullptr, nullptr, nullptr, 0.f, 0.f, 0);
            cudaEventRecord(evT[e], s1);

            // L3: value + RK4 (high-priority stream, overlaps L2t)
            gemm_bf16<1, false><<<gridD, 128, SMEM_SZ, s0>>>(
                h2p, w3b, nullptr, b3, nullptr, 0.f, H_, D_,
                nullptr, nullptr, nullptr, nullptr, nullptr, nullptr,
                xt, xtb, xeb, xacc, cevs[d], wInt[d], d);
        }
    }
    // join: all trace partials final before fold
    cudaStreamWaitEvent(s0, evT[38], 0);
    cudaStreamWaitEvent(s0, evT[39], 0);
    final_kernel<<<B_ / 256, 256, 0, s0>>>(out, w6);

    // join back to capture stream
    cudaEventRecord(evDone, s0);
    cudaStreamWaitEvent((cudaStream_t)0, evDone, 0);
}

// round 16
// speedup vs baseline: 1.3166x; 1.1940x over previous
#include <cuda_runtime.h>
#include <cuda_bf16.h>
#include <cstdint>
#include <cstddef>

#define B_ 16384
#define D_ 256
#define H_ 1024
#define HB_ 8192   // half batch

// ---------------- scratch (device globals: no allocation allowed) ----------------
__device__ float g_noise[B_ * D_];
__device__ __nv_bfloat16 g_z1tb[B_ * H_];
__device__ __nv_bfloat16 g_qb[B_ * H_];
__device__ __nv_bfloat16 g_h1b[B_ * H_];
__device__ __nv_bfloat16 g_dh1b[2][B_ * H_];
__device__ __nv_bfloat16 g_h2b[2][B_ * H_];
__device__ __nv_bfloat16 g_W1b[(D_ + 1) * H_];
__device__ __nv_bfloat16 g_W2b[H_ * H_];
__device__ __nv_bfloat16 g_W3b[H_ * D_];
__device__ __nv_bfloat16 g_W3Tb[D_ * H_];
__device__ float g_trp[40][16][B_];
__device__ float g_xt[B_ * D_];
__device__ __nv_bfloat16 g_xtb[B_ * D_];
__device__ __nv_bfloat16 g_xeb[B_ * D_];
__device__ float g_xacc[B_ * D_];

// ---------------- PTX helpers ----------------
__device__ __forceinline__ uint32_t smem_u32(const void* p) {
    uint32_t a;
    asm("{ .reg .u64 t; cvta.to.shared.u64 t, %1; cvt.u32.u64 %0, t; }" : "=r"(a) : "l"(p));
    return a;
}

__device__ __forceinline__ float tanh_fast(float x) {
    float y;
    asm("tanh.approx.f32 %0, %1;" : "=f"(y) : "f"(x));
    return y;
}

#define CP_ASYNC16(dst, src) \
    asm volatile("cp.async.cg.shared.global [%0], [%1], 16;" :: "r"(dst), "l"(src) : "memory")
#define CP_COMMIT() asm volatile("cp.async.commit_group;" ::: "memory")
#define CP_WAIT(n)  asm volatile("cp.async.wait_group %0;" :: "n"(n) : "memory")

#define LDSM4(r0, r1, r2, r3, a) \
    asm volatile("ldmatrix.sync.aligned.m8n8.x4.shared.b16 {%0,%1,%2,%3}, [%4];" \
        : "=r"(r0), "=r"(r1), "=r"(r2), "=r"(r3) : "r"(a))
#define LDSM4T(r0, r1, r2, r3, a) \
    asm volatile("ldmatrix.sync.aligned.m8n8.x4.trans.shared.b16 {%0,%1,%2,%3}, [%4];" \
        : "=r"(r0), "=r"(r1), "=r"(r2), "=r"(r3) : "r"(a))

#define MMA16816(d, a, b) \
    asm volatile("mma.sync.aligned.m16n8k16.row.col.f32.bf16.bf16.f32 " \
        "{%0,%1,%2,%3}, {%4,%5,%6,%7}, {%8,%9}, {%0,%1,%2,%3};" \
        : "+f"((d)[0]), "+f"((d)[1]), "+f"((d)[2]), "+f"((d)[3]) \
        : "r"((a)[0]), "r"((a)[1]), "r"((a)[2]), "r"((a)[3]), "r"((b)[0]), "r"((b)[1]))

// ---------------- tiling (R10/R13-proven) ----------------
// CTA: 128 threads (4 warps, 2(M) x 2(N)); CTA tile M=128, N=128; warp tile 64x64.
// K-chunk 64, 2-stage pipeline. 3 CTA/SM.
#define A_BYTES   18432          // 128 rows x 144
#define B_BYTES   17408          // 64 rows x 272
#define BUF_S     (A_BYTES + B_BYTES)
#define OFF_AV(b) (512 + (b) * BUF_S)
#define OFF_BB(b) (OFF_AV(b) + A_BYTES)
#define SMEM_SZ   (512 + 2 * BUF_S)

template <bool AFP32>
__device__ __forceinline__ void stage_A(uint32_t sb, int off, const void* Ap,
                                        int K, int m0, int kc, int tid)
{
    if (AFP32) {
        const float* A = (const float*)Ap;
#pragma unroll
        for (int i = 0; i < 8; i++) {
            int id = tid + i * 128;
            int r = id >> 3, q = id & 7;
            const float* s = A + (size_t)(m0 + r) * K + kc + q * 8;
            float4 u = *(const float4*)s;
            float4 v = *(const float4*)(s + 4);
            __nv_bfloat162 p0 = __floats2bfloat162_rn(u.x, u.y);
            __nv_bfloat162 p1 = __floats2bfloat162_rn(u.z, u.w);
            __nv_bfloat162 p2 = __floats2bfloat162_rn(v.x, v.y);
            __nv_bfloat162 p3 = __floats2bfloat162_rn(v.z, v.w);
            uint32_t d = sb + off + r * 144 + q * 16;
            asm volatile("st.shared.v4.b32 [%0], {%1,%2,%3,%4};" :: "r"(d),
                "r"(*(uint32_t*)&p0), "r"(*(uint32_t*)&p1),
                "r"(*(uint32_t*)&p2), "r"(*(uint32_t*)&p3) : "memory");
        }
    } else {
        const __nv_bfloat16* A = (const __nv_bfloat16*)Ap;
#pragma unroll
        for (int i = 0; i < 8; i++) {
            int id = tid + i * 128;
            int r = id >> 3, q = id & 7;
            CP_ASYNC16(sb + off + r * 144 + q * 16,
                       A + (size_t)(m0 + r) * K + kc + q * 8);
        }
    }
}

__device__ __forceinline__ void stage_B(uint32_t sb, int off, const __nv_bfloat16* W,
                                        int Ntot, int n0, int kc, int tid)
{
#pragma unroll
    for (int i = 0; i < 8; i++) {
        int id = tid + i * 128;
        int r = id >> 4, q = id & 15;   // 64 k-rows x 16 x 16B chunks (128 cols)
        CP_ASYNC16(sb + off + r * 272 + q * 16,
                   W + (size_t)(kc + r) * Ntot + n0 + q * 8);
    }
}

// MODE 0: L1  -> Ho=tanh(z+beff) bf16, Do=(1-h^2)*z1t bf16
// MODE 4: L2v -> h2=tanh(z+beff) bf16 -> O1
// MODE 5: L2t -> Trp[16 partials] = sum q*(1-h2^2)*z  (h2 read, mask inline fp32)
// MODE 1: L3  -> v=z+bias; RK4 Xeb/Xacc/Xt
// MODE 2: precompute z1t/q bf16 (blockIdx.x<8 -> Wb/O1, else Wb2/O2), A fp32
template <int MODE, bool AFP32>
__global__ void __launch_bounds__(128, 3)
gemm_bf16(const void* __restrict__ Avp,
          const __nv_bfloat16* __restrict__ Wb, const __nv_bfloat16* __restrict__ Wb2,
          const float* __restrict__ bias, const float* __restrict__ wt, float tval,
          int K, int Ntot,
          void* __restrict__ O1, void* __restrict__ O2,
          const __nv_bfloat16* __restrict__ Z1Tb,
          float* __restrict__ Trp, const __nv_bfloat16* __restrict__ Qb,
          const __nv_bfloat16* __restrict__ H2b,
          float* __restrict__ Xt, __nv_bfloat16* __restrict__ Xtb,
          __nv_bfloat16* __restrict__ Xeb, float* __restrict__ Xacc,
          float cEval, float wInt, int slot)
{
    extern __shared__ char smem[];
    float* beff = (float*)smem;
    const uint32_t sb = smem_u32(smem);
    const int tid = threadIdx.x;
    const int lane = tid & 31, warp = tid >> 5;
    const int m0 = blockIdx.y * 128;
    const int n0 = (MODE == 2) ? (blockIdx.x & 7) * 128 : blockIdx.x * 128;
    const int wm = warp >> 1, wn = warp & 1;          // 2(M) x 2(N) warps

    const __nv_bfloat16* Wu = (MODE == 2 && blockIdx.x >= 8) ? Wb2 : Wb;

    if (MODE != 2 && MODE != 5) {
        float be = bias[n0 + tid];
        if (MODE == 0 && wt) be += tval * wt[n0 + tid];
        beff[tid] = be;
    }

    float acc[4][8][4];                               // 64(M) x 64(N) warp tile
#pragma unroll
    for (int mi = 0; mi < 4; mi++)
#pragma unroll
        for (int ni = 0; ni < 8; ni++)
#pragma unroll
            for (int e = 0; e < 4; e++) acc[mi][ni][e] = 0.f;

    const int NC = K / 64;

    // prologue: stage chunk 0 into buffer 0
    stage_A<AFP32>(sb, OFF_AV(0), Avp, K, m0, 0, tid);
    stage_B(sb, OFF_BB(0), Wu, Ntot, n0, 0, tid);
    CP_COMMIT();

    const int lrow = ((lane >> 3) & 1) * 8 + (lane & 7);   // ldmatrix x4 lane->row
    const int lcol = (lane >> 4) << 4;                     // ldmatrix x4 lane->16B col

    for (int c = 0; c < NC; c++) {
        const int b = c & 1;
        if (c + 1 < NC) {
            const int nb = (c + 1) & 1;
            stage_A<AFP32>(sb, OFF_AV(nb), Avp, K, m0, (c + 1) * 64, tid);
            stage_B(sb, OFF_BB(nb), Wu, Ntot, n0, (c + 1) * 64, tid);
            CP_COMMIT();
            CP_WAIT(1);
        } else {
            CP_WAIT(0);
        }
        __syncthreads();

        const uint32_t aav = sb + OFF_AV(b) + (wm * 64 + lrow) * 144 + lcol;
        const uint32_t abT = sb + OFF_BB(b) + (lane & 15) * 272 + lcol + wn * 128;
#pragma unroll
        for (int kk = 0; kk < 4; kk++) {
            uint32_t av[4][4], bf[4][2];
#pragma unroll
            for (int mi = 0; mi < 4; mi++)
                LDSM4(av[mi][0], av[mi][1], av[mi][2], av[mi][3],
                      aav + mi * 2304 + kk * 32);
            // B in two halves to cap live registers
#pragma unroll
            for (int h = 0; h < 2; h++) {
#pragma unroll
                for (int p = 0; p < 2; p++)
                    LDSM4T(bf[2 * p][0], bf[2 * p][1], bf[2 * p + 1][0], bf[2 * p + 1][1],
                           abT + kk * 4352 + h * 64 + p * 32);
#pragma unroll
                for (int mi = 0; mi < 4; mi++)
#pragma unroll
                    for (int nj = 0; nj < 4; nj++)
                        MMA16816(acc[mi][h * 4 + nj], av[mi], bf[nj]);
            }
        }
        __syncthreads();
    }

    // ---------------- epilogue ----------------
    const int g = lane >> 2, tg = lane & 3;
    float trs[4][2] = {{0.f,0.f},{0.f,0.f},{0.f,0.f},{0.f,0.f}};
#pragma unroll
    for (int mi = 0; mi < 4; mi++)
#pragma unroll
        for (int ni = 0; ni < 8; ni++) {
            const int colp = wn * 64 + ni * 8 + 2 * tg;
            const int colg = n0 + colp;
#pragma unroll
            for (int rh = 0; rh < 2; rh++) {
                const int row = m0 + wm * 64 + mi * 16 + rh * 8 + g;
                const float z0 = acc[mi][ni][rh * 2 + 0];
                const float z1 = acc[mi][ni][rh * 2 + 1];
                if (MODE == 2) {
                    __nv_bfloat16* O = (blockIdx.x < 8) ? (__nv_bfloat16*)O1
                                                        : (__nv_bfloat16*)O2;
                    *(__nv_bfloat162*)(O + (size_t)row * Ntot + colg) =
                        __floats2bfloat162_rn(z0, z1);
                } else if (MODE == 0) {
                    const float h0 = tanh_fast(z0 + beff[colp]);
                    const float h1 = tanh_fast(z1 + beff[colp + 1]);
                    __nv_bfloat162 zt2 =
                        *(const __nv_bfloat162*)(Z1Tb + (size_t)row * Ntot + colg);
                    const float d0 = (1.f - h0 * h0) * __bfloat162float(zt2.x);
                    const float d1 = (1.f - h1 * h1) * __bfloat162float(zt2.y);
                    *(__nv_bfloat162*)((__nv_bfloat16*)O1 + (size_t)row * Ntot + colg) =
                        __floats2bfloat162_rn(h0, h1);
                    *(__nv_bfloat162*)((__nv_bfloat16*)O2 + (size_t)row * Ntot + colg) =
                        __floats2bfloat162_rn(d0, d1);
                } else if (MODE == 4) {
                    const float h0 = tanh_fast(z0 + beff[colp]);
                    const float h1 = tanh_fast(z1 + beff[colp + 1]);
                    *(__nv_bfloat162*)((__nv_bfloat16*)O1 + (size_t)row * Ntot + colg) =
                        __floats2bfloat162_rn(h0, h1);
                } else if (MODE == 5) {
                    __nv_bfloat162 hh =
                        *(const __nv_bfloat162*)(H2b + (size_t)row * Ntot + colg);
                    __nv_bfloat162 q2 =
                        *(const __nv_bfloat162*)(Qb + (size_t)row * Ntot + colg);
                    const float hx = __bfloat162float(hh.x);
                    const float hy = __bfloat162float(hh.y);
                    trs[mi][rh] += __bfloat162float(q2.x) * (1.f - hx * hx) * z0
                                 + __bfloat162float(q2.y) * (1.f - hy * hy) * z1;
                } else {  // MODE 1: L3 value + RK4 integration
                    const float v0 = z0 + beff[colp];
                    const float v1 = z1 + beff[colp + 1];
                    const size_t o = (size_t)row * 256 + colg;
                    if (slot == 0) {
                        float2 a2; a2.x = wInt * v0; a2.y = wInt * v1;
                        *(float2*)(Xacc + o) = a2;
                        float2 x2 = *(const float2*)(Xt + o);
                        *(__nv_bfloat162*)(Xeb + o) =
                            __floats2bfloat162_rn(x2.x + cEval * v0, x2.y + cEval * v1);
                    } else if (slot < 3) {
                        float2 a2 = *(const float2*)(Xacc + o);
                        a2.x += wInt * v0; a2.y += wInt * v1;
                        *(float2*)(Xacc + o) = a2;
                        float2 x2 = *(const float2*)(Xt + o);
                        *(__nv_bfloat162*)(Xeb + o) =
                            __floats2bfloat162_rn(x2.x + cEval * v0, x2.y + cEval * v1);
                    } else {
                        float2 a2 = *(const float2*)(Xacc + o);
                        float2 x2 = *(const float2*)(Xt + o);
                        x2.x += a2.x + wInt * v0;
                        x2.y += a2.y + wInt * v1;
                        *(float2*)(Xt + o) = x2;
                        *(__nv_bfloat162*)(Xtb + o) = __floats2bfloat162_rn(x2.x, x2.y);
                    }
                }
            }
        }
    if (MODE == 5) {
#pragma unroll
        for (int mi = 0; mi < 4; mi++)
#pragma unroll
            for (int rh = 0; rh < 2; rh++) {
                float s = trs[mi][rh];
                s += __shfl_xor_sync(0xffffffffu, s, 1);
                s += __shfl_xor_sync(0xffffffffu, s, 2);
                if (tg == 0) {
                    const int row = m0 + wm * 64 + mi * 16 + rh * 8 + g;
                    Trp[(size_t)(blockIdx.x * 2 + wn) * B_ + row] = s;
                }
            }
    }
}

// ---------------- one-shot prep: weight cvt + W3 transpose + state init ----------------
__global__ void __launch_bounds__(256)
prep_kernel(const float* __restrict__ x,
            const float* __restrict__ W1, const float* __restrict__ W2,
            const float* __restrict__ W3)
{
    int i = blockIdx.x * 256 + threadIdx.x;
    if (i < (D_ + 1) * H_) g_W1b[i] = __float2bfloat16(W1[i]);
    if (i < H_ * H_)       g_W2b[i] = __float2bfloat16(W2[i]);
    if (i < H_ * D_) {
        float w = W3[i];
        g_W3b[i] = __float2bfloat16(w);
        int r = i / D_, c = i % D_;
        g_W3Tb[(size_t)c * H_ + r] = __float2bfloat16(w);
    }
    if (i < B_ * D_) {
        float v = x[i];
        g_xt[i] = v;
        g_xtb[i] = __float2bfloat16(v);
    }
}

// ---------------- noise = sin(1000*(x@proj))*sqrt(2), plain fp32 ----------------
__global__ void __launch_bounds__(256)
noise_kernel(const float* __restrict__ X, const float* __restrict__ P)
{
    __shared__ float As[64][17];
    __shared__ float Bs[16][68];
    int bm = blockIdx.y * 64, bn = blockIdx.x * 64;
    int tx = threadIdx.x, ty = threadIdx.y;
    int tid = ty * 16 + tx;
    float acc[4][4];
#pragma unroll
    for (int i = 0; i < 4; i++)
#pragma unroll
        for (int j = 0; j < 4; j++) acc[i][j] = 0.f;

    for (int k0 = 0; k0 < D_; k0 += 16) {
        int ar = tid >> 2, ac = (tid & 3) * 4;
        float4 a4 = *(const float4*)(X + (size_t)(bm + ar) * D_ + k0 + ac);
        As[ar][ac + 0] = a4.x; As[ar][ac + 1] = a4.y; As[ar][ac + 2] = a4.z; As[ar][ac + 3] = a4.w;
        int br = tid >> 4, bc = (tid & 15) * 4;
        float4 b4 = *(const float4*)(P + (size_t)(k0 + br) * D_ + bn + bc);
        Bs[br][bc + 0] = b4.x; Bs[br][bc + 1] = b4.y; Bs[br][bc + 2] = b4.z; Bs[br][bc + 3] = b4.w;
        __syncthreads();
#pragma unroll
        for (int k = 0; k < 16; k++) {
            float a[4], b[4];
#pragma unroll
            for (int i = 0; i < 4; i++) a[i] = As[ty * 4 + i][k];
#pragma unroll
            for (int j = 0; j < 4; j++) b[j] = Bs[k][tx * 4 + j];
#pragma unroll
            for (int i = 0; i < 4; i++)
#pragma unroll
                for (int j = 0; j < 4; j++) acc[i][j] = fmaf(a[i], b[j], acc[i][j]);
        }
        __syncthreads();
    }
#pragma unroll
    for (int i = 0; i < 4; i++)
#pragma unroll
        for (int j = 0; j < 4; j++)
            g_noise[(size_t)(bm + ty * 4 + i) * D_ + bn + tx * 4 + j] =
                sinf(1000.f * acc[i][j]) * 1.41421356f;
}

// ---------------- final: fold ALL trace partials + log-prob ----------------
__global__ void __launch_bounds__(256)
final_kernel(float* __restrict__ out, float w6)
{
    __shared__ float ljs[256];
    const int r0 = blockIdx.x * 256;
    const int tid = threadIdx.x;
    {
        const int row = r0 + tid;
        float lj = 0.f;
        for (int s = 0; s < 40; s++) {
            float t = 0.f;
#pragma unroll
            for (int p = 0; p < 16; p++) t += g_trp[s][p][row];
            const int sm = s & 3;
            const float c = (sm == 0 || sm == 3) ? w6 : 2.f * w6;
            lj += c * t;
        }
        ljs[tid] = lj;
    }
    __syncthreads();
    const int warp = tid >> 5, lane = tid & 31;
    for (int i = warp; i < 256; i += 8) {
        const int row = r0 + i;
        const float* xr = g_xt + (size_t)row * D_;
        float s = 0.f;
#pragma unroll
        for (int c = 0; c < D_; c += 32) { float v = xr[c + lane]; s += v * v; }
#pragma unroll
        for (int o = 16; o > 0; o >>= 1) s += __shfl_xor_sync(0xffffffffu, s, o);
        if (lane == 0) out[row] = -0.5f * s - 235.2482645f - ljs[i];
    }
}

// ---------------- launch ----------------
extern "C" void kernel_launch(void* const* d_in, const int* in_sizes, int n_in,
                              void* d_out, int out_size)
{
    const float* x  = (const float*)d_in[0];
    const float* W1 = (const float*)d_in[1];
    const float* b1 = (const float*)d_in[2];
    const float* W2 = (const float*)d_in[3];
    const float* b2 = (const float*)d_in[4];
    const float* W3 = (const float*)d_in[5];
    const float* b3 = (const float*)d_in[6];
    const float* pj = (const float*)d_in[7];
    float* out = (float*)d_out;

    float *noise, *trbase, *xt, *xacc;
    __nv_bfloat16 *z1tb, *qb, *h1b, *dh1b, *h2b, *w1b, *w2b, *w3b, *w3tb, *xtb, *xeb;
    cudaGetSymbolAddress((void**)&noise,  g_noise);
    cudaGetSymbolAddress((void**)&z1tb,   g_z1tb);
    cudaGetSymbolAddress((void**)&qb,     g_qb);
    cudaGetSymbolAddress((void**)&h1b,    g_h1b);
    cudaGetSymbolAddress((void**)&dh1b,   g_dh1b);
    cudaGetSymbolAddress((void**)&h2b,    g_h2b);
    cudaGetSymbolAddress((void**)&w1b,    g_W1b);
    cudaGetSymbolAddress((void**)&w2b,    g_W2b);
    cudaGetSymbolAddress((void**)&w3b,    g_W3b);
    cudaGetSymbolAddress((void**)&w3tb,   g_W3Tb);
    cudaGetSymbolAddress((void**)&trbase, g_trp);
    cudaGetSymbolAddress((void**)&xt,     g_xt);
    cudaGetSymbolAddress((void**)&xtb,    g_xtb);
    cudaGetSymbolAddress((void**)&xeb,    g_xeb);
    cudaGetSymbolAddress((void**)&xacc,   g_xacc);

    cudaFuncSetAttribute(gemm_bf16<0, false>, cudaFuncAttributeMaxDynamicSharedMemorySize, SMEM_SZ);
    cudaFuncSetAttribute(gemm_bf16<4, false>, cudaFuncAttributeMaxDynamicSharedMemorySize, SMEM_SZ);
    cudaFuncSetAttribute(gemm_bf16<5, false>, cudaFuncAttributeMaxDynamicSharedMemorySize, SMEM_SZ);
    cudaFuncSetAttribute(gemm_bf16<1, false>, cudaFuncAttributeMaxDynamicSharedMemorySize, SMEM_SZ);
    cudaFuncSetAttribute(gemm_bf16<2, true>,  cudaFuncAttributeMaxDynamicSharedMemorySize, SMEM_SZ);

    // streams: two high-priority pipelines (one per batch half) + one low-priority tangent
    static cudaStream_t s0a = nullptr, s0b = nullptr, s1 = nullptr;
    static cudaEvent_t evA[80], evT[80], evRoot, evDone, evNz, evPre, evB;
    if (s0a == nullptr) {
        int loP, hiP;
        cudaDeviceGetStreamPriorityRange(&loP, &hiP);
        cudaStreamCreateWithPriority(&s0a, cudaStreamNonBlocking, hiP);
        cudaStreamCreateWithPriority(&s0b, cudaStreamNonBlocking, hiP);
        cudaStreamCreateWithPriority(&s1,  cudaStreamNonBlocking, loP);
        for (int i = 0; i < 80; i++) {
            cudaEventCreateWithFlags(&evA[i], cudaEventDisableTiming);
            cudaEventCreateWithFlags(&evT[i], cudaEventDisableTiming);
        }
        cudaEventCreateWithFlags(&evRoot, cudaEventDisableTiming);
        cudaEventCreateWithFlags(&evDone, cudaEventDisableTiming);
        cudaEventCreateWithFlags(&evNz,   cudaEventDisableTiming);
        cudaEventCreateWithFlags(&evPre,  cudaEventDisableTiming);
        cudaEventCreateWithFlags(&evB,    cudaEventDisableTiming);
    }

    // fork from capture stream
    cudaEventRecord(evRoot, (cudaStream_t)0);
    cudaStreamWaitEvent(s0a, evRoot, 0);
    cudaStreamWaitEvent(s1,  evRoot, 0);

    // prologue fork: prep (s0a) || noise (s1); join; z1t/q; release pipeline B
    prep_kernel<<<(B_ * D_) / 256, 256, 0, s0a>>>(x, W1, W2, W3);
    noise_kernel<<<dim3(D_ / 64, B_ / 64), dim3(16, 16), 0, s1>>>(x, pj);
    cudaEventRecord(evNz, s1);
    cudaStreamWaitEvent(s0a, evNz, 0);
    gemm_bf16<2, true><<<dim3(16, B_ / 128), 128, SMEM_SZ, s0a>>>(
        noise, w1b, w3tb, nullptr, nullptr, 0.f, D_, H_,
        z1tb, qb, nullptr, nullptr, nullptr, nullptr,
        nullptr, nullptr, nullptr, nullptr, 0.f, 0.f, 0);
    cudaEventRecord(evPre, s0a);
    cudaStreamWaitEvent(s0b, evPre, 0);

    dim3 gridH(H_ / 128, HB_ / 128);   // 8 x 64 per half
    dim3 gridD(D_ / 128, HB_ / 128);   // 2 x 64 per half

    const float dt = -0.1f;
    const float w6 = dt / 6.f;
    const float wInt[4] = { w6, 2.f * w6, 2.f * w6, w6 };
    for (int k = 0; k < 10; k++) {
        float t = 1.0f + dt * (float)k;
        const float tts[4]  = { t, t + dt * 0.5f, t + dt * 0.5f, t + dt };
        const float cevs[4] = { dt * 0.5f, dt * 0.5f, dt, 0.f };
        for (int d = 0; d < 4; d++) {
            const int e = k * 4 + d;
            const int par = e & 1;
            for (int hf = 0; hf < 2; hf++) {
                cudaStream_t S = hf ? s0b : s0a;
                const int ei = hf * 40 + e;
                const size_t roH = (size_t)hf * HB_ * H_;   // row offset, H-wide bufs
                const size_t roD = (size_t)hf * HB_ * D_;   // row offset, D-wide bufs
                __nv_bfloat16* dh1p = dh1b + (size_t)par * B_ * H_ + roH;
                __nv_bfloat16* h2p  = h2b  + (size_t)par * B_ * H_ + roH;
                __nv_bfloat16* h1p  = h1b + roH;
                const __nv_bfloat16* xin = ((d == 0) ? xtb : xeb) + roD;

                // guard WAR on dh1b/h2b[par] slice vs in-flight L2t(e-2, same half)
                if (e >= 2) cudaStreamWaitEvent(S, evT[ei - 2], 0);

                // L1: h1, dh1[par]
                gemm_bf16<0, false><<<gridH, 128, SMEM_SZ, S>>>(
                    xin, w1b, nullptr, b1, W1 + 256 * H_, tts[d], D_, H_,
                    h1p, dh1p, z1tb + roH, nullptr, nullptr, nullptr,
                    nullptr, nullptr, nullptr, nullptr, 0.f, 0.f, 0);
                // L2 value: h2[par]
                gemm_bf16<4, false><<<gridH, 128, SMEM_SZ, S>>>(
                    h1p, w2b, nullptr, b2, nullptr, 0.f, H_, H_,
                    h2p, nullptr, nullptr, nullptr, nullptr, nullptr,
                    nullptr, nullptr, nullptr, nullptr, 0.f, 0.f, 0);

                // fork: L2 tangent on low-priority s1
                cudaEventRecord(evA[ei], S);
                cudaStreamWaitEvent(s1, evA[ei], 0);
                gemm_bf16<5, false><<<gridH, 128, SMEM_SZ, s1>>>(
                    dh1p, w2b, nullptr, nullptr, nullptr, 0.f, H_, H_,
                    nullptr, nullptr, nullptr,
                    trbase + (size_t)e * 16 * B_ + hf * HB_, qb + roH, h2p,
                    nullptr, nullptr, nullptr, nullptr, 0.f, 0.f, 0);
                cudaEventRecord(evT[ei], s1);

                // L3: value + RK4 (high-priority stream, overlaps L2t)
                gemm_bf16<1, false><<<gridD, 128, SMEM_SZ, S>>>(
                    h2p, w3b, nullptr, b3, nullptr, 0.f, H_, D_,
                    nullptr, nullptr, nullptr, nullptr, nullptr, nullptr,
                    xt + roD, xtb + roD, xeb + roD, xacc + roD,
                    cevs[d], wInt[d], d);
            }
        }
    }
    // join: pipeline B and all trace partials final before fold
    cudaEventRecord(evB, s0b);
    cudaStreamWaitEvent(s0a, evB, 0);
    cudaStreamWaitEvent(s0a, evT[38], 0);
    cudaStreamWaitEvent(s0a, evT[39], 0);
    cudaStreamWaitEvent(s0a, evT[78], 0);
    cudaStreamWaitEvent(s0a, evT[79], 0);
    final_kernel<<<B_ / 256, 256, 0, s0a>>>(out, w6);

    // join back to capture stream
    cudaEventRecord(evDone, s0a);
    cudaStreamWaitEvent((cudaStream_t)0, evDone, 0);
}